// round 9
// baseline (speedup 1.0000x reference)
#include <cuda_runtime.h>
#include <cuda_bf16.h>
#include <cstdint>
#include <math.h>

// AFM fused dual-GEMM kernel, bf16 V + pair-permuted smem (LDS.64 frags),
// bf16 epilogue, GEMM2 interleaved into GEMM1. mma.sync m16n8k16 bf16.
//
// GEMM1: D = VV[16p x 64] @ B^T, B = [W^T(64); p(1); 0(7)] -> N=72
// GEMM2: score = relu(D+bias) @ at_h   (D-frag -> A-frag, same thread)
// acc  += score_g * s1_g  (q4==0 lanes);  out = sigmoid(acc + fm1), fm1 fp32.
//
// smem word permutation: within each 8-word block, word u (o=u&7) sits at
// pos = o<4 ? 2o : 2(o-4)+1  -> frag words (u, u+4) are ADJACENT => LDS.64.

#define F      32
#define BSZ    2048
#define KD     64
#define NPAIR  496
#define NPAD   512
#define NTHR   256
#define NBATCH 2
#define BSTR   144          // sB row stride bytes (36 words)
#define VROW   72           // sV row stride in bf16 (36 words)
#define VNB    (33 * VROW)  // per-batch bf16 count (32 fields + zero row)

#define MMA16816(d, a, bb)                                                      \
    asm volatile("mma.sync.aligned.m16n8k16.row.col.f32.bf16.bf16.f32 "         \
                 "{%0,%1,%2,%3}, {%4,%5,%6,%7}, {%8,%9}, {%0,%1,%2,%3};"        \
                 : "+f"((d)[0]), "+f"((d)[1]), "+f"((d)[2]), "+f"((d)[3])       \
                 : "r"((a)[0]), "r"((a)[1]), "r"((a)[2]), "r"((a)[3]),          \
                   "r"((bb)[0]), "r"((bb)[1]))

#define PACKBF2(res, flo, fhi) \
    asm("cvt.rn.bf16x2.f32 %0, %1, %2;" : "=r"(res) : "f"(fhi), "f"(flo))
#define HMUL2(res, a, b) \
    asm("mul.rn.bf16x2 %0, %1, %2;" : "=r"(res) : "r"(a), "r"(b))
#define HADD2(res, a, b) \
    asm("add.rn.bf16x2 %0, %1, %2;" : "=r"(res) : "r"(a), "r"(b))
#define HMAX2(res, a, b) \
    asm("max.bf16x2 %0, %1, %2;" : "=r"(res) : "r"(a), "r"(b))

// pair permutation: words (u, u+4) within an 8-block become adjacent
__device__ __forceinline__ int permw(int u) {
    const int blk = u >> 3, o = u & 7;
    return blk * 8 + ((o < 4) ? (2 * o) : (2 * (o - 4) + 1));
}

__global__ __launch_bounds__(NTHR, 2)
void afm_bf16p_kernel(const int* __restrict__ x, const float* __restrict__ emb_v,
                      const float* __restrict__ at_w, const float* __restrict__ at_b,
                      const float* __restrict__ at_h, const float* __restrict__ p,
                      const float* __restrict__ w0, const float* __restrict__ w1,
                      float* __restrict__ out)
{
    __shared__ __align__(16) __nv_bfloat16 sVb[NBATCH * VNB];   // ~9.3 KB, permuted
    __shared__ __align__(16) unsigned char sB[72 * BSTR];       // ~10 KB, permuted
    __shared__ uint32_t sBiasPk[32];                            // bf16x2-packed bias
    __shared__ int   sPair[NPAD];
    __shared__ int   sX[NBATCH][F];
    __shared__ float sTot[NBATCH][8];
    __shared__ float sFm1[NBATCH];

    const int b0 = blockIdx.x * NBATCH, tid = threadIdx.x;
    const int w = tid >> 5, lane = tid & 31;
    const int g = lane >> 2, q4 = lane & 3;

    if (tid < NBATCH * F) sX[tid >> 5][tid & 31] = x[(tid & 31) * BSZ + b0 + (tid >> 5)];
    __syncthreads();

    // V gather: float4 -> 2x bf16x2 stored at permuted word positions
    for (int idx = tid; idx < NBATCH * F * 16; idx += NTHR) {
        const int nb = idx >> 9, rem = idx & 511, f = rem >> 4, c = rem & 15;
        const float4 v = ((const float4*)(emb_v + (size_t)sX[nb][f] * KD))[c];
        uint32_t p0, p1;
        PACKBF2(p0, v.x, v.y);
        PACKBF2(p1, v.z, v.w);
        uint32_t* row = (uint32_t*)(sVb + nb * VNB + f * VROW);
        row[permw(2 * c)]     = p0;
        row[permw(2 * c + 1)] = p1;
    }
    if (tid < NBATCH * 18)   // zero row (index 32) per batch
        ((uint2*)(sVb + (tid / 18) * VNB))[32 * 18 + (tid % 18)] = make_uint2(0u, 0u);

    // sB rows 0..63 = W^T, row 64 = p, rows 65..71 = 0 (permuted words)
    for (int idx = tid; idx < KD * KD; idx += NTHR) {
        const int k = idx >> 6, h = idx & 63;
        *(__nv_bfloat16*)(sB + h * BSTR + permw(k >> 1) * 4 + (k & 1) * 2) =
            __float2bfloat16(at_w[idx]);
    }
    if (tid < KD)
        *(__nv_bfloat16*)(sB + 64 * BSTR + permw(tid >> 1) * 4 + (tid & 1) * 2) =
            __float2bfloat16(p[tid]);
    for (int idx = tid; idx < 7 * (BSTR / 4); idx += NTHR) {
        const int row = 65 + idx / (BSTR / 4), c = idx % (BSTR / 4);
        *(uint32_t*)(sB + row * BSTR + c * 4) = 0u;
    }
    if (tid < 32) { uint32_t r; PACKBF2(r, at_b[2 * tid], at_b[2 * tid + 1]); sBiasPk[tid] = r; }
    for (int q = tid; q < NPAD; q += NTHR) {
        if (q < NPAIR) {
            int i = 0, r = q;
            while (r >= F - 1 - i) { r -= F - 1 - i; i++; }
            sPair[q] = (i << 8) | (i + 1 + r);
        } else sPair[q] = (32 << 8) | 32;     // dummy -> zero VV -> s1=0
    }
    if (w >= 8 - NBATCH) {                    // fm1 exact fp32 (dominates logit)
        const int nb = 7 - w;
        float v = w1[sX[nb][lane]];
        #pragma unroll
        for (int off = 16; off; off >>= 1) v += __shfl_xor_sync(0xffffffffu, v, off);
        if (lane == 0) sFm1[nb] = v + w0[0];
    }
    __syncthreads();

    // GEMM1 B fragments in registers (held across both batches): LDS.64 each
    uint32_t Bf[8][4][2];
    #pragma unroll
    for (int nt = 0; nt < 8; nt++)
        #pragma unroll
        for (int ks = 0; ks < 4; ks++) {
            const uint2 v = *(const uint2*)(sB + (nt * 8 + g) * BSTR + (8 * ks + 2 * q4) * 4);
            Bf[nt][ks][0] = v.x;
            Bf[nt][ks][1] = v.y;
        }
    // GEMM2 B fragments: col 0 = at_h, cols 1..7 = 0
    uint32_t Bh[4][2];
    #pragma unroll
    for (int ks = 0; ks < 4; ks++) {
        if (g == 0) {
            const int k0 = ks * 16 + 2 * q4;
            PACKBF2(Bh[ks][0], at_h[k0], at_h[k0 + 1]);
            PACKBF2(Bh[ks][1], at_h[k0 + 8], at_h[k0 + 9]);
        } else { Bh[ks][0] = 0u; Bh[ks][1] = 0u; }
    }

    float accv[NBATCH];
    #pragma unroll 1
    for (int nb = 0; nb < NBATCH; nb++) {
        const __nv_bfloat16* sVn = sVb + nb * VNB;
        float acc = 0.f;
        #pragma unroll
        for (int mt = 0; mt < 4; mt++) {
            const int q0 = w * 64 + mt * 16 + g;
            const int pr0 = sPair[q0], pr1 = sPair[q0 + 8];
            const uint32_t* pi0 = (const uint32_t*)(sVn + (pr0 >> 8) * VROW);
            const uint32_t* pj0 = (const uint32_t*)(sVn + (pr0 & 255) * VROW);
            const uint32_t* pi1 = (const uint32_t*)(sVn + (pr1 >> 8) * VROW);
            const uint32_t* pj1 = (const uint32_t*)(sVn + (pr1 & 255) * VROW);

            // A fragments: 4 LDS.64 + 4 HMUL2 per ks (pair-permuted layout)
            uint32_t Af[4][4];
            #pragma unroll
            for (int ks = 0; ks < 4; ks++) {
                const int u = 8 * ks + 2 * q4;
                const uint2 a0 = *(const uint2*)(pi0 + u);
                const uint2 c0 = *(const uint2*)(pj0 + u);
                const uint2 a1 = *(const uint2*)(pi1 + u);
                const uint2 c1 = *(const uint2*)(pj1 + u);
                HMUL2(Af[ks][0], a0.x, c0.x);
                HMUL2(Af[ks][2], a0.y, c0.y);
                HMUL2(Af[ks][1], a1.x, c1.x);
                HMUL2(Af[ks][3], a1.y, c1.y);
            }

            // s1 tile first (independent MMA chain): streamed B frags, LDS.64
            float ds[4] = {0.f, 0.f, 0.f, 0.f};
            #pragma unroll
            for (int ks = 0; ks < 4; ks++) {
                const uint2 bv = *(const uint2*)(sB + (64 + g) * BSTR + (8 * ks + 2 * q4) * 4);
                uint32_t b8[2] = { bv.x, bv.y };
                MMA16816(ds, Af[ks], b8);
            }

            // GEMM1 nt pairs with GEMM2 interleaved; two independent dd chains
            float dd0[4] = {0.f, 0.f, 0.f, 0.f}, dd1[4] = {0.f, 0.f, 0.f, 0.f};
            #pragma unroll
            for (int ksp = 0; ksp < 4; ksp++) {
                uint32_t A2[4];
                #pragma unroll
                for (int half = 0; half < 2; half++) {
                    const int nt = 2 * ksp + half;
                    float d[4] = {0.f, 0.f, 0.f, 0.f};
                    #pragma unroll
                    for (int ks = 0; ks < 4; ks++) MMA16816(d, Af[ks], Bf[nt][ks]);
                    uint32_t h01, h23;
                    PACKBF2(h01, d[0], d[1]);
                    PACKBF2(h23, d[2], d[3]);
                    const uint32_t bp = sBiasPk[nt * 4 + q4];
                    HADD2(h01, h01, bp); HADD2(h23, h23, bp);
                    HMAX2(h01, h01, 0u); HMAX2(h23, h23, 0u);
                    A2[2 * half] = h01; A2[2 * half + 1] = h23;
                }
                if (ksp & 1) { MMA16816(dd1, A2, Bh[ksp]); }
                else         { MMA16816(dd0, A2, Bh[ksp]); }
            }
            acc = fmaf(dd0[0] + dd1[0], ds[0], fmaf(dd0[2] + dd1[2], ds[2], acc));
        }
        accv[nb] = acc;
    }

    #pragma unroll
    for (int nb = 0; nb < NBATCH; nb++) {
        float r = accv[nb];
        #pragma unroll
        for (int off = 16; off; off >>= 1) r += __shfl_xor_sync(0xffffffffu, r, off);
        if (lane == 0) sTot[nb][w] = r;
    }
    __syncthreads();
    if (tid < NBATCH) {
        float t = sFm1[tid];
        #pragma unroll
        for (int k = 0; k < 8; k++) t += sTot[tid][k];
        out[b0 + tid] = 1.f / (1.f + expf(-t));
    }
}

extern "C" void kernel_launch(void* const* d_in, const int* in_sizes, int n_in,
                              void* d_out, int out_size)
{
    (void)in_sizes; (void)n_in; (void)out_size;
    afm_bf16p_kernel<<<BSZ / NBATCH, NTHR>>>(
        (const int*)  d_in[0],   // x      [F, B]
        (const float*)d_in[1],   // emb_v  [VOCAB, K]
        (const float*)d_in[2],   // at_w   [K, H]
        (const float*)d_in[3],   // at_b   [H]
        (const float*)d_in[4],   // at_h   [H, 1]
        (const float*)d_in[5],   // p      [K, 1]
        (const float*)d_in[6],   // w0     scalar
        (const float*)d_in[7],   // w1     [VOCAB, 1]
        (float*)d_out);
}